// round 16
// baseline (speedup 1.0000x reference)
#include <cuda_runtime.h>
#include <cooperative_groups.h>
#include <cstdint>

namespace cg = cooperative_groups;

#define H     100
#define G4    400
#define TSEQ  8192
#define FUT   1024
#define TOT   (TSEQ + FUT)
#define NSLOT 8
#define NTHR  480
#define SIGA  416     // warp 13 lane 0: signaler / single-waiter
#define SIGB  448     // warp 14: y-reduction warp (L2 CTA)

typedef unsigned long long u64;

// Communication block — identical static smem layout in every cluster CTA.
// h1ring+fullh+freep live in rk1 (Pa) and rk2 (Pb); pring+fullp live in rk3 (L2);
// ybuf+fully+freeh live in rk0 (L1).
struct __align__(16) Comm {
    float h1ring[NSLOT][128];   // in Pa/Pb, written by L1 via st.async
    float pring [NSLOT][400];   // in L2: rows 0-199 from Pa, 200-399 from Pb
    float ybuf[2];              // in L1, written by L2 via st.async
    u64   fullh[NSLOT];         // in Pa/Pb: h1 slot data-arrived (count 1)
    u64   freeh[NSLOT];         // in L1: h1 slot consumed (count 2: Pa+Pb)
    u64   fullp[NSLOT];         // in L2: p slot data-arrived (count 2: Pa+Pb)
    u64   freep[NSLOT];         // in Pa/Pb: p slot consumed (count 1)
    u64   fully[2];             // in L1: y arrived (count 1)
};

// ---- address helpers ----
static __device__ __forceinline__ uint32_t sm2u(const void* p) {
    uint32_t a;
    asm("{ .reg .u64 t; cvta.to.shared.u64 t, %1; cvt.u32.u64 %0, t; }" : "=r"(a) : "l"(p));
    return a;
}
static __device__ __forceinline__ uint32_t mapa_(uint32_t a, uint32_t rank) {
    uint32_t o; asm("mapa.shared::cluster.u32 %0, %1, %2;" : "=r"(o) : "r"(a), "r"(rank));
    return o;
}
// ---- mbarrier ops ----
static __device__ __forceinline__ void mbar_init(uint32_t a, uint32_t cnt) {
    asm volatile("mbarrier.init.shared.b64 [%0], %1;" :: "r"(a), "r"(cnt) : "memory");
}
static __device__ __forceinline__ void mbar_wait(uint32_t a, uint32_t parity) {
    asm volatile(
        "{\n\t.reg .pred P;\n\t"
        "WL%=:\n\t"
        "mbarrier.try_wait.parity.acquire.cluster.shared::cta.b64 P, [%0], %1, 0x989680;\n\t"
        "@P bra.uni WD%=;\n\t"
        "bra.uni WL%=;\n\t"
        "WD%=:\n\t}"
        :: "r"(a), "r"(parity) : "memory");
}
static __device__ __forceinline__ void arrive_tx_remote(uint32_t ra, uint32_t tx) {
    asm volatile("mbarrier.arrive.expect_tx.shared::cluster.b64 _, [%0], %1;"
                 :: "r"(ra), "r"(tx) : "memory");
}
static __device__ __forceinline__ void arrive_remote(uint32_t ra) {
    asm volatile("mbarrier.arrive.shared::cluster.b64 _, [%0];" :: "r"(ra) : "memory");
}
static __device__ __forceinline__ void st_async_f32(uint32_t ra, float v, uint32_t rmbar) {
    asm volatile("st.async.shared::cluster.mbarrier::complete_tx::bytes.b32 [%0], %1, [%2];"
                 :: "r"(ra), "r"(__float_as_uint(v)), "r"(rmbar) : "memory");
}
static __device__ __forceinline__ void ffma2(u64& a, u64 w, u64 h) {
    asm("fma.rn.f32x2 %0, %1, %2, %3;" : "=l"(a) : "l"(w), "l"(h), "l"(a));
}
static __device__ __forceinline__ float f2lo(u64 a) { return __uint_as_float((unsigned)a); }
static __device__ __forceinline__ float f2hi(u64 a) { return __uint_as_float((unsigned)(a >> 32)); }
static __device__ __forceinline__ float sigm(float x)  { return __fdividef(1.0f, 1.0f + __expf(-x)); }
static __device__ __forceinline__ float tanh_(float x) { return __fdividef(2.0f, 1.0f + __expf(-2.0f * x)) - 1.0f; }

// 100-wide dot: 25 LDS.128 + 50 packed f32x2 FMAs against register weights.
static __device__ __forceinline__ float dot100(const u64* W, const float* sh) {
    const ulonglong2* h = (const ulonglong2*)sh;
    u64 a0 = 0ull, a1 = 0ull;
#pragma unroll
    for (int j = 0; j < 25; j++) {
        ulonglong2 hv = h[j];
        ffma2(a0, W[2 * j],     hv.x);
        ffma2(a1, W[2 * j + 1], hv.y);
    }
    return f2lo(a0) + f2hi(a0) + f2lo(a1) + f2hi(a1);
}

__global__ void __launch_bounds__(NTHR, 1)
lstm_decoder_kernel(
    const float* __restrict__ input,
    const float* __restrict__ enc_h,
    const float* __restrict__ enc_c,
    const float* __restrict__ w_ih1,
    const float* __restrict__ w_hh1,
    const float* __restrict__ b_ih1,
    const float* __restrict__ b_hh1,
    const float* __restrict__ w_ih2,
    const float* __restrict__ w_hh2,
    const float* __restrict__ b_ih2,
    const float* __restrict__ b_hh2,
    const float* __restrict__ w_lin,
    const float* __restrict__ b_lin,
    float* __restrict__ out)
{
    cg::cluster_group cluster = cg::this_cluster();
    const unsigned rk = cluster.block_rank();

    __shared__ Comm cm;
    __shared__ __align__(16) float sx[TSEQ];   // L1 only: staged input
    __shared__ __align__(16) float shA[128];   // L1: h1 state; L2: h2 state
    __shared__ float sg[400];
    __shared__ float swi[400];                 // L1: w_ih1 staged (future-phase x terms)
    __shared__ float swl[112];
    __shared__ float syp[2][112];

    const int t = threadIdx.x;

    // local mbar base addresses
    const uint32_t a_fullh = sm2u(cm.fullh);
    const uint32_t a_freeh = sm2u(cm.freeh);
    const uint32_t a_fullp = sm2u(cm.fullp);
    const uint32_t a_freep = sm2u(cm.freep);
    const uint32_t a_fully = sm2u(cm.fully);

    if (t == 0) {
        for (int s = 0; s < NSLOT; s++) {
            mbar_init(a_fullh + s * 8, 1);   // single producer arrival (L1 SIGA)
            mbar_init(a_freeh + s * 8, 2);   // Pa + Pb acks
            mbar_init(a_fullp + s * 8, 2);   // Pa + Pb arrivals
            mbar_init(a_freep + s * 8, 1);   // L2 ack
        }
        mbar_init(a_fully, 1);
        mbar_init(a_fully + 8, 1);
    }
    __syncthreads();
    cluster.sync();   // all mbarriers initialized cluster-wide before any async traffic

    if (rk == 0) {
        // ======================= L1: layer-1 LSTM =======================
        const uint32_t r_h1a = mapa_(sm2u(cm.h1ring), 1);
        const uint32_t r_h1b = mapa_(sm2u(cm.h1ring), 2);
        const uint32_t r_fha = mapa_(a_fullh, 1);
        const uint32_t r_fhb = mapa_(a_fullh, 2);
        u64 Wr[50];
        float wi = 0.f, bb = 0.f, c1s = 0.f;
        if (t < G4) {
            const u64* wp = (const u64*)(w_hh1 + t * H);
#pragma unroll
            for (int j = 0; j < 50; j++) Wr[j] = wp[j];
            wi = w_ih1[t];
            bb = b_ih1[t] + b_hh1[t];
            swi[t] = wi;                                    // staged for future-phase act path
        }
        for (int i = t; i < TSEQ; i += NTHR) sx[i] = input[i];
        if (t < H) { shA[t] = enc_h[t]; c1s = enc_c[t]; }
        __syncthreads();

        for (int step = 0; step < TOT; ++step) {
            const int slot = step & (NSLOT - 1);
            if (t == SIGA) {
                // EARLY ARM: legal — freeh(slot) was observed by this thread last step
                arrive_tx_remote(r_fha + slot * 8, 400);
                arrive_tx_remote(r_fhb + slot * 8, 400);
                // future: y-wait hidden under the 400-thread dot
                if (step >= TSEQ) {
                    const int fi = step - TSEQ;
                    mbar_wait(a_fully + (fi & 1) * 8, (fi >> 1) & 1);
                }
                // lookahead backpressure for next step's slot
                if (step + 1 >= NSLOT && step + 1 < TOT) {
                    const int s2 = step + 1;
                    mbar_wait(a_freeh + (s2 & (NSLOT - 1)) * 8, ((s2 >> 3) + 1) & 1);
                }
            }
            if (t < G4) {
                float a = dot100(Wr, shA) + bb;
                if (step < TSEQ) a = fmaf(sx[step], wi, a);  // seq: inline x (cheap, parallel)
                sg[t] = a;
            }
            __syncthreads();                                 // B1 (also broadcasts ybuf acquire)
            if (t < H) {
                float ig = sg[t], fg = sg[t + 100], gg = sg[t + 200], og = sg[t + 300];
                if (step >= TSEQ) {                          // future: apply x terms here
                    float x = cm.ybuf[(step - TSEQ) & 1];
                    ig = fmaf(x, swi[t],       ig);
                    fg = fmaf(x, swi[t + 100], fg);
                    gg = fmaf(x, swi[t + 200], gg);
                    og = fmaf(x, swi[t + 300], og);
                }
                c1s = sigm(fg) * c1s + sigm(ig) * tanh_(gg);
                float hh = sigm(og) * tanh_(c1s);
                shA[t] = hh;
                st_async_f32(r_h1a + (slot * 128 + t) * 4, hh, r_fha + slot * 8);
                st_async_f32(r_h1b + (slot * 128 + t) * 4, hh, r_fhb + slot * 8);
            }
            __syncthreads();                                 // B2 (orders shA for next dot)
        }
    } else if (rk == 1 || rk == 2) {
        // ======= Pa / Pb: p[rows] = W_ih2 @ h1 + b2 — 200 rows, ONE thread per row =======
        const int rowbase = (int)(rk - 1) * 200;
        const uint32_t r_p     = mapa_(sm2u(cm.pring), 3);
        const uint32_t r_fullp = mapa_(a_fullp, 3);
        const uint32_t r_freeh = mapa_(a_freeh, 0);
        const int prow = rowbase + t;                        // valid for t < 200
        u64 W[50];
        float bb = 0.f;
        if (t < 200) {
            const u64* wp = (const u64*)(w_ih2 + prow * H);
#pragma unroll
            for (int j = 0; j < 50; j++) W[j] = wp[j];
            bb = b_ih2[prow] + b_hh2[prow];
        }
        __syncthreads();

        for (int step = 0; step < TOT; ++step) {
            const int slot = step & (NSLOT - 1);
            if (t < 200) {
                mbar_wait(a_fullh + slot * 8, (step >> 3) & 1); // h1(step) landed locally
                float p = dot100(W, cm.h1ring[slot]) + bb;
                st_async_f32(r_p + (slot * 400 + prow) * 4, p, r_fullp + slot * 8);
            } else if (t == SIGA) {
                // EARLY ARM for this step's p slot (freep(slot) observed last step)
                arrive_tx_remote(r_fullp + slot * 8, 800);
                // lookahead: pring slot reuse for next step
                if (step + 1 >= NSLOT && step + 1 < TOT) {
                    const int s2 = step + 1;
                    mbar_wait(a_freep + (s2 & (NSLOT - 1)) * 8, ((s2 >> 3) + 1) & 1);
                }
            }
            __syncthreads();                                 // single barrier/step
            if (t == SIGA && step < TOT - NSLOT)
                arrive_remote(r_freeh + slot * 8);           // h1(step) consumed (1 of 2)
        }
    } else {
        // ======================= L2: layer-2 recurrence + output =======================
        const uint32_t r_fpa   = mapa_(a_freep, 1);
        const uint32_t r_fpb   = mapa_(a_freep, 2);
        const uint32_t r_ybuf  = mapa_(sm2u(cm.ybuf), 0);
        const uint32_t r_fully = mapa_(a_fully, 0);
        u64 Wr[50];
        float c2s = 0.f;
        if (t < G4) {
            const u64* wp = (const u64*)(w_hh2 + t * H);
#pragma unroll
            for (int j = 0; j < 50; j++) Wr[j] = wp[j];
        }
        if (t < H) { shA[t] = 0.f; swl[t] = w_lin[t]; }
        const float blin = b_lin[0];
        __syncthreads();
        // prologue: observe p(0) before the first un-waited read
        if (t == SIGA) mbar_wait(a_fullp + 0, 0);
        __syncthreads();

        for (int step = 0; step < TOT; ++step) {
            const int slot = step & (NSLOT - 1);
            const int sel  = step & 1;
            if (t < G4) {
                float q = dot100(Wr, shA);                   // q-dot (local h2 only)
                // seq: fullp(step) already observed via SIGA lookahead last step (no wait).
                // future: current-step wait (lookahead would close the y-feedback cycle).
                if (step >= TSEQ)
                    mbar_wait(a_fullp + slot * 8, (step >> 3) & 1);
                sg[t] = q + cm.pring[slot][t];
            }
            __syncthreads();                                 // B1 (p consumed)
            if (t == SIGA) {
                if (step < TOT - NSLOT) {
                    arrive_remote(r_fpa + slot * 8);         // acks first — P can proceed
                    arrive_remote(r_fpb + slot * 8);
                }
                if (step + 1 < TSEQ) {                       // seq-phase lookahead only
                    const int s2 = step + 1;
                    mbar_wait(a_fullp + (s2 & (NSLOT - 1)) * 8, (s2 >> 3) & 1);
                }
            }
            if (t < H) {
                float ig = sg[t], fg = sg[t + 100], gg = sg[t + 200], og = sg[t + 300];
                c2s = sigm(fg) * c2s + sigm(ig) * tanh_(gg);
                float hh = sigm(og) * tanh_(c2s);
                shA[t] = hh;
                syp[sel][t] = hh * swl[t];
            }
            __syncthreads();                                 // B2
            if (t >= SIGB) {                                 // warp 14: y reduction
                int sl = t - SIGB;
                const float* sp = syp[sel];
                float v = 0.f;
                if (sl < 25) {
                    int b4 = 4 * sl;
                    v = sp[b4] + sp[b4 + 1] + sp[b4 + 2] + sp[b4 + 3];
                }
                v += __shfl_xor_sync(0xffffffffu, v, 16);
                v += __shfl_xor_sync(0xffffffffu, v, 8);
                v += __shfl_xor_sync(0xffffffffu, v, 4);
                v += __shfl_xor_sync(0xffffffffu, v, 2);
                v += __shfl_xor_sync(0xffffffffu, v, 1);
                if (sl == 0) {
                    float y = v + blin;
                    out[step] = y;
                    if (step >= TSEQ - 1 && step < TOT - 1) {   // skip final y (never consumed)
                        const int fi = step - (TSEQ - 1);
                        st_async_f32(r_ybuf + (fi & 1) * 4, y, r_fully + (fi & 1) * 8);
                        arrive_tx_remote(r_fully + (fi & 1) * 8, 4);
                    }
                }
            }
        }
    }

    cluster.sync();   // lifetime guard: no CTA exits while peers may still write its SMEM
}

extern "C" void kernel_launch(void* const* d_in, const int* in_sizes, int n_in,
                              void* d_out, int out_size) {
    (void)in_sizes; (void)n_in; (void)out_size;
    const float* input = (const float*)d_in[0];
    const float* eh    = (const float*)d_in[1];
    const float* ec    = (const float*)d_in[2];
    const float* wih1  = (const float*)d_in[3];
    const float* whh1  = (const float*)d_in[4];
    const float* bih1  = (const float*)d_in[5];
    const float* bhh1  = (const float*)d_in[6];
    const float* wih2  = (const float*)d_in[7];
    const float* whh2  = (const float*)d_in[8];
    const float* bih2  = (const float*)d_in[9];
    const float* bhh2  = (const float*)d_in[10];
    const float* wlin  = (const float*)d_in[11];
    const float* blin  = (const float*)d_in[12];
    float* out = (float*)d_out;

    cudaLaunchConfig_t cfg = {};
    cfg.gridDim  = dim3(4, 1, 1);
    cfg.blockDim = dim3(NTHR, 1, 1);
    cfg.dynamicSmemBytes = 0;
    cudaLaunchAttribute attrs[1];
    attrs[0].id = cudaLaunchAttributeClusterDimension;
    attrs[0].val.clusterDim.x = 4;
    attrs[0].val.clusterDim.y = 1;
    attrs[0].val.clusterDim.z = 1;
    cfg.attrs = attrs;
    cfg.numAttrs = 1;

    cudaLaunchKernelEx(&cfg, lstm_decoder_kernel,
                       input, eh, ec, wih1, whh1, bih1, bhh1,
                       wih2, whh2, bih2, bhh2, wlin, blin, out);
}

// round 17
// speedup vs baseline: 1.6512x; 1.6512x over previous
#include <cuda_runtime.h>
#include <cooperative_groups.h>
#include <cstdint>

namespace cg = cooperative_groups;

#define H     100
#define G4    400
#define TSEQ  8192
#define FUT   1024
#define TOT   (TSEQ + FUT)
#define NSLOT 8
#define NTHR  480
#define SIGA  416     // warp 13 lane 0: signaler / single-waiter
#define SIGB  448     // warp 14: y-reduction warp (L2 CTA)

typedef unsigned long long u64;

// Communication block — identical static smem layout in every cluster CTA.
// h1ring+fullh+freep live in rk1 (Pa) and rk2 (Pb); pring+fullp live in rk3 (L2);
// ybuf+fully+freeh live in rk0 (L1).
struct __align__(16) Comm {
    float h1ring[NSLOT][128];   // in Pa/Pb, written by L1 via st.async
    float pring [NSLOT][400];   // in L2: rows 0-199 from Pa, 200-399 from Pb
    float ybuf[2];              // in L1, written by L2 via st.async
    u64   fullh[NSLOT];         // in Pa/Pb: h1 slot data-arrived (count 1)
    u64   freeh[NSLOT];         // in L1: h1 slot consumed (count 2: Pa+Pb)
    u64   fullp[NSLOT];         // in L2: p slot data-arrived (count 2: Pa+Pb)
    u64   freep[NSLOT];         // in Pa/Pb: p slot consumed (count 1)
    u64   fully[2];             // in L1: y arrived (count 1)
};

// ---- address helpers ----
static __device__ __forceinline__ uint32_t sm2u(const void* p) {
    uint32_t a;
    asm("{ .reg .u64 t; cvta.to.shared.u64 t, %1; cvt.u32.u64 %0, t; }" : "=r"(a) : "l"(p));
    return a;
}
static __device__ __forceinline__ uint32_t mapa_(uint32_t a, uint32_t rank) {
    uint32_t o; asm("mapa.shared::cluster.u32 %0, %1, %2;" : "=r"(o) : "r"(a), "r"(rank));
    return o;
}
// ---- mbarrier ops ----
static __device__ __forceinline__ void mbar_init(uint32_t a, uint32_t cnt) {
    asm volatile("mbarrier.init.shared.b64 [%0], %1;" :: "r"(a), "r"(cnt) : "memory");
}
static __device__ __forceinline__ void mbar_wait(uint32_t a, uint32_t parity) {
    asm volatile(
        "{\n\t.reg .pred P;\n\t"
        "WL%=:\n\t"
        "mbarrier.try_wait.parity.acquire.cluster.shared::cta.b64 P, [%0], %1, 0x989680;\n\t"
        "@P bra.uni WD%=;\n\t"
        "bra.uni WL%=;\n\t"
        "WD%=:\n\t}"
        :: "r"(a), "r"(parity) : "memory");
}
static __device__ __forceinline__ void arrive_tx_remote(uint32_t ra, uint32_t tx) {
    asm volatile("mbarrier.arrive.expect_tx.shared::cluster.b64 _, [%0], %1;"
                 :: "r"(ra), "r"(tx) : "memory");
}
static __device__ __forceinline__ void arrive_remote(uint32_t ra) {
    asm volatile("mbarrier.arrive.shared::cluster.b64 _, [%0];" :: "r"(ra) : "memory");
}
static __device__ __forceinline__ void st_async_f32(uint32_t ra, float v, uint32_t rmbar) {
    asm volatile("st.async.shared::cluster.mbarrier::complete_tx::bytes.b32 [%0], %1, [%2];"
                 :: "r"(ra), "r"(__float_as_uint(v)), "r"(rmbar) : "memory");
}
static __device__ __forceinline__ void ffma2(u64& a, u64 w, u64 h) {
    asm("fma.rn.f32x2 %0, %1, %2, %3;" : "=l"(a) : "l"(w), "l"(h), "l"(a));
}
static __device__ __forceinline__ float f2lo(u64 a) { return __uint_as_float((unsigned)a); }
static __device__ __forceinline__ float f2hi(u64 a) { return __uint_as_float((unsigned)(a >> 32)); }
static __device__ __forceinline__ float sigm(float x)  { return __fdividef(1.0f, 1.0f + __expf(-x)); }
static __device__ __forceinline__ float tanh_(float x) { return __fdividef(2.0f, 1.0f + __expf(-2.0f * x)) - 1.0f; }

// 100-wide dot: 25 LDS.128 + 50 packed f32x2 FMAs against register weights.
static __device__ __forceinline__ float dot100(const u64* W, const float* sh) {
    const ulonglong2* h = (const ulonglong2*)sh;
    u64 a0 = 0ull, a1 = 0ull;
#pragma unroll
    for (int j = 0; j < 25; j++) {
        ulonglong2 hv = h[j];
        ffma2(a0, W[2 * j],     hv.x);
        ffma2(a1, W[2 * j + 1], hv.y);
    }
    return f2lo(a0) + f2hi(a0) + f2lo(a1) + f2hi(a1);
}

__global__ void __launch_bounds__(NTHR, 1)
lstm_decoder_kernel(
    const float* __restrict__ input,
    const float* __restrict__ enc_h,
    const float* __restrict__ enc_c,
    const float* __restrict__ w_ih1,
    const float* __restrict__ w_hh1,
    const float* __restrict__ b_ih1,
    const float* __restrict__ b_hh1,
    const float* __restrict__ w_ih2,
    const float* __restrict__ w_hh2,
    const float* __restrict__ b_ih2,
    const float* __restrict__ b_hh2,
    const float* __restrict__ w_lin,
    const float* __restrict__ b_lin,
    float* __restrict__ out)
{
    cg::cluster_group cluster = cg::this_cluster();
    const unsigned rk = cluster.block_rank();

    __shared__ Comm cm;
    __shared__ __align__(16) float sx[TSEQ];   // L1 only: staged input
    __shared__ __align__(16) float shA[128];   // L1: h1 state; L2: h2 state
    __shared__ float sg[400];
    __shared__ float swi[400];                 // L1: w_ih1 staged (future-phase x terms)
    __shared__ float swl[112];
    __shared__ float syp[2][112];

    const int t = threadIdx.x;

    // local mbar base addresses
    const uint32_t a_fullh = sm2u(cm.fullh);
    const uint32_t a_freeh = sm2u(cm.freeh);
    const uint32_t a_fullp = sm2u(cm.fullp);
    const uint32_t a_freep = sm2u(cm.freep);
    const uint32_t a_fully = sm2u(cm.fully);

    if (t == 0) {
        for (int s = 0; s < NSLOT; s++) {
            mbar_init(a_fullh + s * 8, 1);   // single producer arrival (L1 SIGA)
            mbar_init(a_freeh + s * 8, 2);   // Pa + Pb acks
            mbar_init(a_fullp + s * 8, 2);   // Pa + Pb arrivals
            mbar_init(a_freep + s * 8, 1);   // L2 ack
        }
        mbar_init(a_fully, 1);
        mbar_init(a_fully + 8, 1);
    }
    __syncthreads();
    cluster.sync();   // all mbarriers initialized cluster-wide before any async traffic

    if (rk == 0) {
        // ======================= L1: layer-1 LSTM =======================
        const uint32_t r_h1a = mapa_(sm2u(cm.h1ring), 1);
        const uint32_t r_h1b = mapa_(sm2u(cm.h1ring), 2);
        const uint32_t r_fha = mapa_(a_fullh, 1);
        const uint32_t r_fhb = mapa_(a_fullh, 2);
        u64 Wr[50];
        float wi = 0.f, bb = 0.f, c1s = 0.f;
        if (t < G4) {
            const u64* wp = (const u64*)(w_hh1 + t * H);
#pragma unroll
            for (int j = 0; j < 50; j++) Wr[j] = wp[j];
            wi = w_ih1[t];
            bb = b_ih1[t] + b_hh1[t];
            swi[t] = wi;                                     // staged for future-phase act path
        }
        for (int i = t; i < TSEQ; i += NTHR) sx[i] = input[i];
        if (t < H) { shA[t] = enc_h[t]; c1s = enc_c[t]; }
        __syncthreads();

        for (int step = 0; step < TOT; ++step) {
            const int slot = step & (NSLOT - 1);
            if (t == SIGA) {
                // EARLY ARM: legal — freeh(slot) was observed by this thread last step
                arrive_tx_remote(r_fha + slot * 8, 400);
                arrive_tx_remote(r_fhb + slot * 8, 400);
                // future: y-wait hidden under the 400-thread dot
                if (step >= TSEQ) {
                    const int fi = step - TSEQ;
                    mbar_wait(a_fully + (fi & 1) * 8, (fi >> 1) & 1);
                }
                // lookahead backpressure (FREE ack, 5 steps of slack — non-serializing)
                if (step + 1 >= NSLOT && step + 1 < TOT) {
                    const int s2 = step + 1;
                    mbar_wait(a_freeh + (s2 & (NSLOT - 1)) * 8, ((s2 >> 3) + 1) & 1);
                }
            }
            if (t < G4) {
                float a = dot100(Wr, shA) + bb;
                if (step < TSEQ) a = fmaf(sx[step], wi, a);  // seq: inline x
                sg[t] = a;
            }
            __syncthreads();                                 // B1 (broadcasts ybuf acquire too)
            if (t < H) {
                float ig = sg[t], fg = sg[t + 100], gg = sg[t + 200], og = sg[t + 300];
                if (step >= TSEQ) {                          // future: apply x terms here
                    float x = cm.ybuf[(step - TSEQ) & 1];
                    ig = fmaf(x, swi[t],       ig);
                    fg = fmaf(x, swi[t + 100], fg);
                    gg = fmaf(x, swi[t + 200], gg);
                    og = fmaf(x, swi[t + 300], og);
                }
                c1s = sigm(fg) * c1s + sigm(ig) * tanh_(gg);
                float hh = sigm(og) * tanh_(c1s);
                shA[t] = hh;
                st_async_f32(r_h1a + (slot * 128 + t) * 4, hh, r_fha + slot * 8);
                st_async_f32(r_h1b + (slot * 128 + t) * 4, hh, r_fhb + slot * 8);
            }
            __syncthreads();                                 // B2 (orders shA for next dot)
        }
    } else if (rk == 1 || rk == 2) {
        // ======= Pa / Pb: p[rows] = W_ih2 @ h1 + b2 — 200 rows, ONE thread per row =======
        const int rowbase = (int)(rk - 1) * 200;
        const uint32_t r_p     = mapa_(sm2u(cm.pring), 3);
        const uint32_t r_fullp = mapa_(a_fullp, 3);
        const uint32_t r_freeh = mapa_(a_freeh, 0);
        const int prow = rowbase + t;                        // valid for t < 200
        u64 W[50];
        float bb = 0.f;
        if (t < 200) {
            const u64* wp = (const u64*)(w_ih2 + prow * H);
#pragma unroll
            for (int j = 0; j < 50; j++) W[j] = wp[j];
            bb = b_ih2[prow] + b_hh2[prow];
        }
        __syncthreads();

        for (int step = 0; step < TOT; ++step) {
            const int slot = step & (NSLOT - 1);
            if (t < 200) {
                mbar_wait(a_fullh + slot * 8, (step >> 3) & 1); // h1(step) landed locally
                float p = dot100(W, cm.h1ring[slot]) + bb;
                st_async_f32(r_p + (slot * 400 + prow) * 4, p, r_fullp + slot * 8);
            } else if (t == SIGA) {
                // EARLY ARM: legal — freep(slot) observed by this thread last step
                arrive_tx_remote(r_fullp + slot * 8, 800);
                // lookahead backpressure (FREE ack, 5 steps of slack — non-serializing)
                if (step + 1 >= NSLOT && step + 1 < TOT) {
                    const int s2 = step + 1;
                    mbar_wait(a_freep + (s2 & (NSLOT - 1)) * 8, ((s2 >> 3) + 1) & 1);
                }
            }
            __syncthreads();                                 // single barrier/step
            if (t == SIGA && step < TOT - NSLOT)
                arrive_remote(r_freeh + slot * 8);           // h1(step) consumed (1 of 2)
        }
    } else {
        // ============== L2: layer-2 recurrence + output (EXACT R15 form) ==============
        const uint32_t r_fpa   = mapa_(a_freep, 1);
        const uint32_t r_fpb   = mapa_(a_freep, 2);
        const uint32_t r_ybuf  = mapa_(sm2u(cm.ybuf), 0);
        const uint32_t r_fully = mapa_(a_fully, 0);
        u64 Wr[50];
        float c2s = 0.f;
        if (t < G4) {
            const u64* wp = (const u64*)(w_hh2 + t * H);
#pragma unroll
            for (int j = 0; j < 50; j++) Wr[j] = wp[j];
        }
        if (t < H) { shA[t] = 0.f; swl[t] = w_lin[t]; }
        const float blin = b_lin[0];
        __syncthreads();

        for (int step = 0; step < TOT; ++step) {
            const int slot = step & (NSLOT - 1);
            const int sel  = step & 1;
            if (t < G4) {
                float q = dot100(Wr, shA);                   // q-dot FIRST (local h2 only)
                mbar_wait(a_fullp + slot * 8, (step >> 3) & 1); // then p (overlaps upstream hop)
                sg[t] = q + cm.pring[slot][t];
            }
            __syncthreads();                                 // B1 (p consumed)
            if (t == SIGA && step < TOT - NSLOT) {
                arrive_remote(r_fpa + slot * 8);
                arrive_remote(r_fpb + slot * 8);
            }
            if (t < H) {
                float ig = sg[t], fg = sg[t + 100], gg = sg[t + 200], og = sg[t + 300];
                c2s = sigm(fg) * c2s + sigm(ig) * tanh_(gg);
                float hh = sigm(og) * tanh_(c2s);
                shA[t] = hh;
                syp[sel][t] = hh * swl[t];
            }
            __syncthreads();                                 // B2
            if (t >= SIGB) {                                 // warp 14: y reduction
                int sl = t - SIGB;
                const float* sp = syp[sel];
                float v = 0.f;
                if (sl < 25) {
                    int b4 = 4 * sl;
                    v = sp[b4] + sp[b4 + 1] + sp[b4 + 2] + sp[b4 + 3];
                }
                v += __shfl_xor_sync(0xffffffffu, v, 16);
                v += __shfl_xor_sync(0xffffffffu, v, 8);
                v += __shfl_xor_sync(0xffffffffu, v, 4);
                v += __shfl_xor_sync(0xffffffffu, v, 2);
                v += __shfl_xor_sync(0xffffffffu, v, 1);
                if (sl == 0) {
                    float y = v + blin;
                    out[step] = y;
                    if (step >= TSEQ - 1 && step < TOT - 1) {   // skip final y (never consumed)
                        const int fi = step - (TSEQ - 1);
                        st_async_f32(r_ybuf + (fi & 1) * 4, y, r_fully + (fi & 1) * 8);
                        arrive_tx_remote(r_fully + (fi & 1) * 8, 4);
                    }
                }
            }
        }
    }

    cluster.sync();   // lifetime guard: no CTA exits while peers may still write its SMEM
}

extern "C" void kernel_launch(void* const* d_in, const int* in_sizes, int n_in,
                              void* d_out, int out_size) {
    (void)in_sizes; (void)n_in; (void)out_size;
    const float* input = (const float*)d_in[0];
    const float* eh    = (const float*)d_in[1];
    const float* ec    = (const float*)d_in[2];
    const float* wih1  = (const float*)d_in[3];
    const float* whh1  = (const float*)d_in[4];
    const float* bih1  = (const float*)d_in[5];
    const float* bhh1  = (const float*)d_in[6];
    const float* wih2  = (const float*)d_in[7];
    const float* whh2  = (const float*)d_in[8];
    const float* bih2  = (const float*)d_in[9];
    const float* bhh2  = (const float*)d_in[10];
    const float* wlin  = (const float*)d_in[11];
    const float* blin  = (const float*)d_in[12];
    float* out = (float*)d_out;

    cudaLaunchConfig_t cfg = {};
    cfg.gridDim  = dim3(4, 1, 1);
    cfg.blockDim = dim3(NTHR, 1, 1);
    cfg.dynamicSmemBytes = 0;
    cudaLaunchAttribute attrs[1];
    attrs[0].id = cudaLaunchAttributeClusterDimension;
    attrs[0].val.clusterDim.x = 4;
    attrs[0].val.clusterDim.y = 1;
    attrs[0].val.clusterDim.z = 1;
    cfg.attrs = attrs;
    cfg.numAttrs = 1;

    cudaLaunchKernelEx(&cfg, lstm_decoder_kernel,
                       input, eh, ec, wih1, whh1, bih1, bhh1,
                       wih2, whh2, bih2, bhh2, wlin, blin, out);
}